// round 16
// baseline (speedup 1.0000x reference)
#include <cuda_runtime.h>
#include <cuda_bf16.h>

// ChannelPruner: out[b,o,h,w] = sum_c w[o,c] * x[b,c,h,w]
// x: (32, 256, 56, 56) fp32, w: (256, 256, 1, 1) fp32.
// Persistent single-wave variant of the R14 kernel: 1216 CTAs (152 SM x 8)
// each loop over ~7 (b,o) planes. Per-plane work identical to R14's proven
// hot path (warp-local shfl-scan compaction, zero block barriers). Goal:
// eliminate ~6 wave transitions + per-CTA launch/drain overhead that leave
// DRAM idle 38% of the time.

#define N_CH   256
#define HW4    784            // 56*56/4 float4 per plane
#define NBATCH 32
#define PLANES (N_CH * NBATCH)   // 8192
#define NCTA   1216              // 152 SMs * 8 resident CTAs

__global__ __launch_bounds__(256, 8)
void channel_pruner_kernel(const float4* __restrict__ X,
                           const float4* __restrict__ W,   // row o = W[o*64 .. o*64+63]
                           float4* __restrict__ O)
{
    const int tid  = threadIdx.x;   // 256 threads
    const int wid  = tid >> 5;      // warp 0..7
    const int lane = tid & 31;

    // per-warp private compaction slices (8 warps x 256 entries)
    __shared__ int   s_c[8][N_CH];
    __shared__ float s_v[8][N_CH];

    int*   const wcm = s_c[wid];
    float* const wvm = s_v[wid];
    const size_t planeStride = (size_t)N_CH * HW4;

    for (int p = blockIdx.x; p < PLANES; p += NCTA) {
        const int o = p & (N_CH - 1);
        const int b = p >> 8;

        // --- warp-local scan of w row o (each warp does the full row) ---
        // lane l owns float4 indices {2l, 2l+1} = channels 8l..8l+7.
        const float4 wa = __ldg(&W[o * 64 + lane * 2]);
        const float4 wb = __ldg(&W[o * 64 + lane * 2 + 1]);
        const int cnt = (wa.x != 0.0f) + (wa.y != 0.0f) + (wa.z != 0.0f) + (wa.w != 0.0f)
                      + (wb.x != 0.0f) + (wb.y != 0.0f) + (wb.z != 0.0f) + (wb.w != 0.0f);

        int incl = cnt;
        #pragma unroll
        for (int d = 1; d < 32; d <<= 1) {
            int t = __shfl_up_sync(0xFFFFFFFFu, incl, d);
            if (lane >= d) incl += t;
        }
        const int nnz = __shfl_sync(0xFFFFFFFFu, incl, 31);
        int q = incl - cnt;                 // exclusive offset

        if (cnt > 0) {
            const int cbase = lane * 8;
            if (wa.x != 0.0f) { wcm[q] = cbase + 0; wvm[q] = wa.x; q++; }
            if (wa.y != 0.0f) { wcm[q] = cbase + 1; wvm[q] = wa.y; q++; }
            if (wa.z != 0.0f) { wcm[q] = cbase + 2; wvm[q] = wa.z; q++; }
            if (wa.w != 0.0f) { wcm[q] = cbase + 3; wvm[q] = wa.w; q++; }
            if (wb.x != 0.0f) { wcm[q] = cbase + 4; wvm[q] = wb.x; q++; }
            if (wb.y != 0.0f) { wcm[q] = cbase + 5; wvm[q] = wb.y; q++; }
            if (wb.z != 0.0f) { wcm[q] = cbase + 6; wvm[q] = wb.z; q++; }
            if (wb.w != 0.0f) { wcm[q] = cbase + 7; wvm[q] = wb.w; q++; }
        }
        __syncwarp();   // slice visible to all lanes of this warp

        const float4* __restrict__ Xb = X + (size_t)b * planeStride;
        float4* __restrict__ Ob = O + (size_t)b * planeStride + (size_t)o * HW4;

        // --- stream the plane (identical to R14 hot path) ---
        if (nnz == 0) {
            const float4 z = make_float4(0.f, 0.f, 0.f, 0.f);
            Ob[tid]       = z;
            Ob[tid + 256] = z;
            Ob[tid + 512] = z;
            if (tid < HW4 - 768) Ob[tid + 768] = z;
        } else if (nnz == 1) {
            const float v = wvm[0];
            const float4* __restrict__ Xc = Xb + (size_t)wcm[0] * HW4;
            float4 a0 = __ldg(&Xc[tid]);
            float4 a1 = __ldg(&Xc[tid + 256]);
            float4 a2 = __ldg(&Xc[tid + 512]);
            float4 a3;
            if (tid < HW4 - 768) a3 = __ldg(&Xc[tid + 768]);
            a0.x *= v; a0.y *= v; a0.z *= v; a0.w *= v;
            a1.x *= v; a1.y *= v; a1.z *= v; a1.w *= v;
            a2.x *= v; a2.y *= v; a2.z *= v; a2.w *= v;
            Ob[tid]       = a0;
            Ob[tid + 256] = a1;
            Ob[tid + 512] = a2;
            if (tid < HW4 - 768) {
                a3.x *= v; a3.y *= v; a3.z *= v; a3.w *= v;
                Ob[tid + 768] = a3;
            }
        } else {
            for (int s = tid; s < HW4; s += 256) {
                float4 acc = make_float4(0.f, 0.f, 0.f, 0.f);
                for (int k = 0; k < nnz; k++) {
                    const float v = wvm[k];
                    const float4 xv = __ldg(&Xb[(size_t)wcm[k] * HW4 + s]);
                    acc.x += v * xv.x;
                    acc.y += v * xv.y;
                    acc.z += v * xv.z;
                    acc.w += v * xv.w;
                }
                Ob[s] = acc;
            }
        }
        __syncwarp();   // all lanes done reading slice before next overwrite
    }
}

extern "C" void kernel_launch(void* const* d_in, const int* in_sizes, int n_in,
                              void* d_out, int out_size)
{
    const float4* X = (const float4*)d_in[0];   // x: 32*256*56*56 fp32
    const float4* W = (const float4*)d_in[1];   // conv_weights: 256*256*1*1 fp32
    float4* O = (float4*)d_out;

    channel_pruner_kernel<<<NCTA, 256>>>(X, W, O);   // persistent single wave
}

// round 17
// speedup vs baseline: 1.0611x; 1.0611x over previous
#include <cuda_runtime.h>
#include <cuda_bf16.h>
#include <cstdint>

// ChannelPruner: out[b,o,h,w] = sum_c w[o,c] * x[b,c,h,w]
// x: (32, 256, 56, 56) fp32, w: (256, 256, 1, 1) fp32.
// R14 structure (8192 blocks x 256 thr, warp-local shfl-scan compaction,
// zero block barriers) + ONE isolated change: output stores are 256-bit
// st.global.L2::evict_first.v4.b64 — write-once output lines yield L2 first,
// so x's live set stays resident across graph replays (kills the ~20MB/replay
// read-miss tax). Loads remain plain 128-bit __ldg (R12 showed the 256-bit
// load path costs ALU/L1 overhead).

#define N_CH   256
#define HW4    784          // 56*56/4 float4 per plane
#define HW8    392          // 32B units per plane (392 = 256 + 136)
#define NBATCH 32

struct f8 { float4 a, b; };

__device__ __forceinline__ void stg_ef8(void* p, const f8& v) {
    asm volatile("st.global.L2::evict_first.v4.b64 [%0], {%1,%2,%3,%4};"
                 :: "l"(p),
                    "d"(*(const double*)&v.a.x), "d"(*(const double*)&v.a.z),
                    "d"(*(const double*)&v.b.x), "d"(*(const double*)&v.b.z)
                 : "memory");
}

__global__ __launch_bounds__(256, 8)
void channel_pruner_kernel(const float4* __restrict__ X,
                           const float4* __restrict__ W,   // row o = W[o*64 .. o*64+63]
                           float4* __restrict__ O)
{
    const int o    = blockIdx.x;    // output channel
    const int b    = blockIdx.y;    // batch
    const int tid  = threadIdx.x;   // 256 threads
    const int wid  = tid >> 5;      // warp 0..7
    const int lane = tid & 31;

    // per-warp private compaction slices (8 warps x 256 entries)
    __shared__ int   s_c[8][N_CH];
    __shared__ float s_v[8][N_CH];

    // --- Phase 1: warp-local scan of w row o (each warp does the full row) ---
    const float4 wa = __ldg(&W[o * 64 + lane * 2]);
    const float4 wb = __ldg(&W[o * 64 + lane * 2 + 1]);
    const int cnt = (wa.x != 0.0f) + (wa.y != 0.0f) + (wa.z != 0.0f) + (wa.w != 0.0f)
                  + (wb.x != 0.0f) + (wb.y != 0.0f) + (wb.z != 0.0f) + (wb.w != 0.0f);

    int incl = cnt;
    #pragma unroll
    for (int d = 1; d < 32; d <<= 1) {
        int t = __shfl_up_sync(0xFFFFFFFFu, incl, d);
        if (lane >= d) incl += t;
    }
    const int nnz = __shfl_sync(0xFFFFFFFFu, incl, 31);
    int q = incl - cnt;                 // exclusive offset

    if (cnt > 0) {
        const int cbase = lane * 8;
        int*   wc = s_c[wid];
        float* wv = s_v[wid];
        if (wa.x != 0.0f) { wc[q] = cbase + 0; wv[q] = wa.x; q++; }
        if (wa.y != 0.0f) { wc[q] = cbase + 1; wv[q] = wa.y; q++; }
        if (wa.z != 0.0f) { wc[q] = cbase + 2; wv[q] = wa.z; q++; }
        if (wa.w != 0.0f) { wc[q] = cbase + 3; wv[q] = wa.w; q++; }
        if (wb.x != 0.0f) { wc[q] = cbase + 4; wv[q] = wb.x; q++; }
        if (wb.y != 0.0f) { wc[q] = cbase + 5; wv[q] = wb.y; q++; }
        if (wb.z != 0.0f) { wc[q] = cbase + 6; wv[q] = wb.z; q++; }
        if (wb.w != 0.0f) { wc[q] = cbase + 7; wv[q] = wb.w; q++; }
    }
    __syncwarp();

    const int*   wc = s_c[wid];
    const float* wv = s_v[wid];

    const size_t planeStride = (size_t)N_CH * HW4;
    const float4* __restrict__ Xb = X + (size_t)b * planeStride;
    float4* __restrict__ Ob = O + (size_t)b * planeStride + (size_t)o * HW4;

    const bool has1 = (tid < HW8 - 256);   // second 32B unit valid?

    // --- Phase 2: stream the plane; stores are 32B evict_first bursts ---
    if (nnz == 0) {
        f8 z; z.a = make_float4(0.f,0.f,0.f,0.f); z.b = z.a;
        stg_ef8(&Ob[2 * tid], z);
        if (has1) stg_ef8(&Ob[2 * (tid + 256)], z);
    } else if (nnz == 1) {
        const float v = wv[0];
        const float4* __restrict__ Xc = Xb + (size_t)wc[0] * HW4;
        // loads paired to match 32B store units; all issued before stores
        f8 x0, x1;
        x0.a = __ldg(&Xc[2 * tid]);
        x0.b = __ldg(&Xc[2 * tid + 1]);
        if (has1) {
            x1.a = __ldg(&Xc[2 * (tid + 256)]);
            x1.b = __ldg(&Xc[2 * (tid + 256) + 1]);
        }
        x0.a.x *= v; x0.a.y *= v; x0.a.z *= v; x0.a.w *= v;
        x0.b.x *= v; x0.b.y *= v; x0.b.z *= v; x0.b.w *= v;
        stg_ef8(&Ob[2 * tid], x0);
        if (has1) {
            x1.a.x *= v; x1.a.y *= v; x1.a.z *= v; x1.a.w *= v;
            x1.b.x *= v; x1.b.y *= v; x1.b.z *= v; x1.b.w *= v;
            stg_ef8(&Ob[2 * (tid + 256)], x1);
        }
    } else {
        // generic sparse accumulation over 32B units
        for (int u = tid; u < HW8; u += 256) {
            f8 acc;
            acc.a = make_float4(0.f,0.f,0.f,0.f);
            acc.b = acc.a;
            for (int k = 0; k < nnz; k++) {
                const float v = wv[k];
                const float4* __restrict__ Xc = Xb + (size_t)wc[k] * HW4;
                const float4 xa = __ldg(&Xc[2 * u]);
                const float4 xb = __ldg(&Xc[2 * u + 1]);
                acc.a.x += v * xa.x; acc.a.y += v * xa.y;
                acc.a.z += v * xa.z; acc.a.w += v * xa.w;
                acc.b.x += v * xb.x; acc.b.y += v * xb.y;
                acc.b.z += v * xb.z; acc.b.w += v * xb.w;
            }
            stg_ef8(&Ob[2 * u], acc);
        }
    }
}

extern "C" void kernel_launch(void* const* d_in, const int* in_sizes, int n_in,
                              void* d_out, int out_size)
{
    const float4* X = (const float4*)d_in[0];   // x: 32*256*56*56 fp32
    const float4* W = (const float4*)d_in[1];   // conv_weights: 256*256*1*1 fp32
    float4* O = (float4*)d_out;

    dim3 grid(N_CH, NBATCH);    // 8192 blocks: one per (b, o) plane
    channel_pruner_kernel<<<grid, 256>>>(X, W, O);
}